// round 1
// baseline (speedup 1.0000x reference)
#include <cuda_runtime.h>
#include <math.h>

#define S_LEN  2048
#define G_GRP  2
#define EMB    1024
#define NH     16
#define NKV    4
#define HD     64
#define MROWS  (S_LEN * G_GRP)      // 4096
#define KVW    (NKV * HD)           // 256
#define ROWQ   (G_GRP * EMB)        // 2048  (row stride of Q/O buffers)
#define ROWK   (G_GRP * KVW)        // 512   (row stride of K/V buffers)

// ---------------- scratch (no allocation allowed) ----------------
__device__ float g_Q[MROWS * EMB];
__device__ float g_K[MROWS * KVW];
__device__ float g_V[MROWS * KVW];
__device__ float g_O[MROWS * EMB];

// ---------------- 128x128 SGEMM tile body ----------------
// A: [M,K] row-major, B: [K,ldn] row-major, C: [M,ldn] row-major.
// Computes C[m0:m0+128, col0:col0+128] for K inner dim.
__device__ __forceinline__ void gemm_tile_128(
    const float* __restrict__ A, const float* __restrict__ B, float* __restrict__ C,
    int K, int ldn, int m0, int col0)
{
    __shared__ float As[16][132];   // transposed, padded
    __shared__ float Bs[16][128];

    const int tid = threadIdx.x;        // 0..255
    const int ty  = tid >> 4;           // 0..15  -> rows ty*8..+7
    const int tx  = tid & 15;           // 0..15  -> cols tx*8..+7

    float acc[8][8];
#pragma unroll
    for (int i = 0; i < 8; i++)
#pragma unroll
        for (int j = 0; j < 8; j++) acc[i][j] = 0.0f;

    for (int k0 = 0; k0 < K; k0 += 16) {
        // load A tile 128x16 (transposed into As[k][m])
#pragma unroll
        for (int p = 0; p < 2; p++) {
            int arow = (tid >> 2) + p * 64;      // 0..127
            int ac4  = tid & 3;                  // 0..3
            float4 a = *reinterpret_cast<const float4*>(&A[(size_t)(m0 + arow) * K + k0 + ac4 * 4]);
            As[ac4 * 4 + 0][arow] = a.x;
            As[ac4 * 4 + 1][arow] = a.y;
            As[ac4 * 4 + 2][arow] = a.z;
            As[ac4 * 4 + 3][arow] = a.w;
        }
        // load B tile 16x128
#pragma unroll
        for (int p = 0; p < 2; p++) {
            int idx  = tid + p * 256;
            int brow = idx >> 5;                 // 0..15
            int bc4  = idx & 31;                 // 0..31
            float4 b = *reinterpret_cast<const float4*>(&B[(size_t)(k0 + brow) * ldn + col0 + bc4 * 4]);
            *reinterpret_cast<float4*>(&Bs[brow][bc4 * 4]) = b;
        }
        __syncthreads();

#pragma unroll
        for (int kk = 0; kk < 16; kk++) {
            float a[8], b[8];
            *reinterpret_cast<float4*>(a)     = *reinterpret_cast<const float4*>(&As[kk][ty * 8]);
            *reinterpret_cast<float4*>(a + 4) = *reinterpret_cast<const float4*>(&As[kk][ty * 8 + 4]);
            *reinterpret_cast<float4*>(b)     = *reinterpret_cast<const float4*>(&Bs[kk][tx * 8]);
            *reinterpret_cast<float4*>(b + 4) = *reinterpret_cast<const float4*>(&Bs[kk][tx * 8 + 4]);
#pragma unroll
            for (int i = 0; i < 8; i++)
#pragma unroll
                for (int j = 0; j < 8; j++)
                    acc[i][j] = fmaf(a[i], b[j], acc[i][j]);
        }
        __syncthreads();
    }

#pragma unroll
    for (int i = 0; i < 8; i++) {
        int m = m0 + ty * 8 + i;
#pragma unroll
        for (int j4 = 0; j4 < 2; j4++) {
            float4 v = make_float4(acc[i][j4 * 4], acc[i][j4 * 4 + 1],
                                   acc[i][j4 * 4 + 2], acc[i][j4 * 4 + 3]);
            *reinterpret_cast<float4*>(&C[(size_t)m * ldn + col0 + tx * 8 + j4 * 4]) = v;
        }
    }
}

// ---------------- fused QKV projection ----------------
// grid.x = 12 (8 Q tiles, 2 K tiles, 2 V tiles of 128 cols), grid.y = 32 (M tiles)
__global__ __launch_bounds__(256) void qkv_gemm(
    const float* __restrict__ X,
    const float* __restrict__ Wq, const float* __restrict__ Wk, const float* __restrict__ Wv)
{
    const int nb = blockIdx.x;
    const float* B; float* C; int ldn; int col0;
    if (nb < 8)       { B = Wq; C = g_Q; ldn = EMB; col0 = nb * 128; }
    else if (nb < 10) { B = Wk; C = g_K; ldn = KVW; col0 = (nb - 8) * 128; }
    else              { B = Wv; C = g_V; ldn = KVW; col0 = (nb - 10) * 128; }
    gemm_tile_128(X, B, C, EMB, ldn, blockIdx.y * 128, col0);
}

// ---------------- output projection ----------------
__global__ __launch_bounds__(256) void oproj_gemm(
    const float* __restrict__ Wo, float* __restrict__ out)
{
    gemm_tile_128(g_O, Wo, out, EMB, EMB, blockIdx.y * 128, blockIdx.x * 128);
}

// ---------------- flash attention (causal, per (g,h) head) ----------------
// BM = BN = 64, D = 64, 128 threads (16 ty x 8 tx), each thread 4 rows x 8 cols.
#define FA_SMEM ((3 * 64 * 65 + 64 * 64) * 4)

__global__ __launch_bounds__(128) void flash_kernel()
{
    extern __shared__ float sm[];
    float* Qt = sm;                 // [64][65]  Qt[d][r]
    float* Kt = Qt + 64 * 65;       // [64][65]  Kt[d][c]
    float* Ps = Kt + 64 * 65;       // [64][65]  Ps[r][c]
    float* Vs = Ps + 64 * 65;       // [64][64]  Vs[c][d]

    const int tid = threadIdx.x;
    const int ty  = tid >> 3;       // 0..15
    const int tx  = tid & 7;        // 0..7
    const int ty4 = ty * 4;
    const int tx8 = tx * 8;

    const int qb  = blockIdx.x;     // query block 0..31
    const int gh  = blockIdx.y;     // 0..31
    const int g   = gh & 1;
    const int h   = gh >> 1;
    const int kvh = h >> 2;         // ratio = 4

    const float* Qp = g_Q + g * EMB + h * HD;
    const float* Kp = g_K + g * KVW + kvh * HD;
    const float* Vp = g_V + g * KVW + kvh * HD;
    float*       Op = g_O + g * EMB + h * HD;

    const int q0 = qb * 64;
    const float scale = 0.125f;     // 1/sqrt(64)

    // load Q block transposed
#pragma unroll
    for (int p = 0; p < 8; p++) {
        int idx = tid + p * 128;
        int r   = idx >> 4;
        int d4  = idx & 15;
        float4 q = *reinterpret_cast<const float4*>(&Qp[(size_t)(q0 + r) * ROWQ + d4 * 4]);
        Qt[(d4 * 4 + 0) * 65 + r] = q.x;
        Qt[(d4 * 4 + 1) * 65 + r] = q.y;
        Qt[(d4 * 4 + 2) * 65 + r] = q.z;
        Qt[(d4 * 4 + 3) * 65 + r] = q.w;
    }

    float m_i[4], l_i[4], acc[4][8];
#pragma unroll
    for (int i = 0; i < 4; i++) {
        m_i[i] = -1e30f; l_i[i] = 0.0f;
#pragma unroll
        for (int j = 0; j < 8; j++) acc[i][j] = 0.0f;
    }
    __syncthreads();

    for (int kb = 0; kb <= qb; kb++) {
        const int kn = kb * 64;
        // load K transposed + V natural
#pragma unroll
        for (int p = 0; p < 8; p++) {
            int idx = tid + p * 128;
            int c   = idx >> 4;
            int d4  = idx & 15;
            float4 k = *reinterpret_cast<const float4*>(&Kp[(size_t)(kn + c) * ROWK + d4 * 4]);
            Kt[(d4 * 4 + 0) * 65 + c] = k.x;
            Kt[(d4 * 4 + 1) * 65 + c] = k.y;
            Kt[(d4 * 4 + 2) * 65 + c] = k.z;
            Kt[(d4 * 4 + 3) * 65 + c] = k.w;
            float4 v = *reinterpret_cast<const float4*>(&Vp[(size_t)(kn + c) * ROWK + d4 * 4]);
            *reinterpret_cast<float4*>(&Vs[c * 64 + d4 * 4]) = v;
        }
        __syncthreads();

        // S = Q K^T
        float s[4][8];
#pragma unroll
        for (int i = 0; i < 4; i++)
#pragma unroll
            for (int j = 0; j < 8; j++) s[i][j] = 0.0f;

#pragma unroll 4
        for (int d = 0; d < 64; d++) {
            float qv[4], kv[8];
#pragma unroll
            for (int i = 0; i < 4; i++) qv[i] = Qt[d * 65 + ty4 + i];
#pragma unroll
            for (int j = 0; j < 8; j++) kv[j] = Kt[d * 65 + tx8 + j];
#pragma unroll
            for (int i = 0; i < 4; i++)
#pragma unroll
                for (int j = 0; j < 8; j++)
                    s[i][j] = fmaf(qv[i], kv[j], s[i][j]);
        }

        const bool diag = (kb == qb);
        // scale + causal mask + online softmax
#pragma unroll
        for (int i = 0; i < 4; i++) {
            const int qi = q0 + ty4 + i;
#pragma unroll
            for (int j = 0; j < 8; j++) {
                float sv = s[i][j] * scale;
                if (diag && (kn + tx8 + j) > qi) sv = -1e30f;
                s[i][j] = sv;
            }
            float mx = s[i][0];
#pragma unroll
            for (int j = 1; j < 8; j++) mx = fmaxf(mx, s[i][j]);
            mx = fmaxf(mx, __shfl_xor_sync(0xffffffffu, mx, 1));
            mx = fmaxf(mx, __shfl_xor_sync(0xffffffffu, mx, 2));
            mx = fmaxf(mx, __shfl_xor_sync(0xffffffffu, mx, 4));
            float m_new = fmaxf(m_i[i], mx);
            float alpha = __expf(m_i[i] - m_new);
            float psum = 0.0f;
#pragma unroll
            for (int j = 0; j < 8; j++) {
                float p = __expf(s[i][j] - m_new);
                s[i][j] = p;
                psum += p;
            }
            psum += __shfl_xor_sync(0xffffffffu, psum, 1);
            psum += __shfl_xor_sync(0xffffffffu, psum, 2);
            psum += __shfl_xor_sync(0xffffffffu, psum, 4);
            l_i[i] = l_i[i] * alpha + psum;
            m_i[i] = m_new;
#pragma unroll
            for (int j = 0; j < 8; j++) {
                acc[i][j] *= alpha;
                Ps[(ty4 + i) * 65 + tx8 + j] = s[i][j];
            }
        }
        __syncthreads();

        // acc += P @ V
#pragma unroll 2
        for (int c = 0; c < 64; c++) {
            float pv[4];
#pragma unroll
            for (int i = 0; i < 4; i++) pv[i] = Ps[(ty4 + i) * 65 + c];
            float4 v0 = *reinterpret_cast<const float4*>(&Vs[c * 64 + tx8]);
            float4 v1 = *reinterpret_cast<const float4*>(&Vs[c * 64 + tx8 + 4]);
            float vv[8] = {v0.x, v0.y, v0.z, v0.w, v1.x, v1.y, v1.z, v1.w};
#pragma unroll
            for (int i = 0; i < 4; i++)
#pragma unroll
                for (int j = 0; j < 8; j++)
                    acc[i][j] = fmaf(pv[i], vv[j], acc[i][j]);
        }
        __syncthreads();
    }

    // epilogue: normalize and write O
#pragma unroll
    for (int i = 0; i < 4; i++) {
        float inv = 1.0f / l_i[i];
        float4 o0 = make_float4(acc[i][0] * inv, acc[i][1] * inv, acc[i][2] * inv, acc[i][3] * inv);
        float4 o1 = make_float4(acc[i][4] * inv, acc[i][5] * inv, acc[i][6] * inv, acc[i][7] * inv);
        size_t base = (size_t)(q0 + ty4 + i) * ROWQ + tx8;
        *reinterpret_cast<float4*>(&Op[base])     = o0;
        *reinterpret_cast<float4*>(&Op[base + 4]) = o1;
    }
}

// ---------------- launch ----------------
extern "C" void kernel_launch(void* const* d_in, const int* in_sizes, int n_in,
                              void* d_out, int out_size)
{
    const float* x  = (const float*)d_in[0];
    const float* Wq = (const float*)d_in[1];
    const float* Wk = (const float*)d_in[2];
    const float* Wv = (const float*)d_in[3];
    const float* Wo = (const float*)d_in[4];
    float* out = (float*)d_out;

    cudaFuncSetAttribute(flash_kernel, cudaFuncAttributeMaxDynamicSharedMemorySize, FA_SMEM);

    qkv_gemm<<<dim3(12, 32), 256>>>(x, Wq, Wk, Wv);
    flash_kernel<<<dim3(32, 32), 128, FA_SMEM>>>();
    oproj_gemm<<<dim3(8, 32), 256>>>(Wo, out);
}

// round 3
// speedup vs baseline: 1.7676x; 1.7676x over previous
#include <cuda_runtime.h>
#include <cstdint>
#include <math.h>

#define S_LEN  2048
#define G_GRP  2
#define EMB    1024
#define NH     16
#define NKV    4
#define HD     64
#define MROWS  (S_LEN * G_GRP)      // 4096
#define KVW    (NKV * HD)           // 256
#define ROWQ   (G_GRP * EMB)        // 2048
#define ROWK   (G_GRP * KVW)        // 512

// ---------------- scratch (no allocation allowed) ----------------
__device__ float g_Q[MROWS * EMB];
__device__ float g_K[MROWS * KVW];
__device__ float g_V[MROWS * KVW];
__device__ float g_O[MROWS * EMB];
__device__ float g_WT[(EMB + 2 * KVW) * EMB];   // fused [1536][1024] transposed weights
__device__ float g_WoT[EMB * EMB];

// ================= mma.sync tf32 helpers (sm_80+, legal on sm_103) ==========
__device__ __forceinline__ uint32_t f2tf32(float x) {
    uint32_t r;
    asm("cvt.rna.tf32.f32 %0, %1;" : "=r"(r) : "f"(x));
    return r;
}

__device__ __forceinline__ void mma_tf32(float c[4], const uint32_t a[4], const uint32_t b[2]) {
    asm volatile(
        "mma.sync.aligned.m16n8k8.row.col.f32.tf32.tf32.f32 "
        "{%0,%1,%2,%3}, {%4,%5,%6,%7}, {%8,%9}, {%0,%1,%2,%3};"
        : "+f"(c[0]), "+f"(c[1]), "+f"(c[2]), "+f"(c[3])
        : "r"(a[0]), "r"(a[1]), "r"(a[2]), "r"(a[3]), "r"(b[0]), "r"(b[1]));
}

// ================= weight transpose: W[K][N] -> WT[N][K] =====================
__global__ __launch_bounds__(1024) void transpose32(const float* __restrict__ W,
                                                    float* __restrict__ WT, int N, int K) {
    __shared__ float t[32][33];
    int n = blockIdx.x * 32 + threadIdx.x;
    int k = blockIdx.y * 32 + threadIdx.y;
    t[threadIdx.y][threadIdx.x] = W[(size_t)k * N + n];
    __syncthreads();
    int n2 = blockIdx.x * 32 + threadIdx.y;
    int k2 = blockIdx.y * 32 + threadIdx.x;
    WT[(size_t)n2 * K + k2] = t[threadIdx.x][threadIdx.y];
}

// ================= tf32 mma GEMM: 128x128 tile, K = 1024 =====================
// A: [M][1024] row-major; BT: [Nfused][1024] row-major (so BT[n][k] == B[k][n]).
// C tile at C[m0..+127][c0..+127], row stride ldc.
#define AST 36   // smem row stride (floats): (row*36 + col) % 32 lane-unique

__device__ __forceinline__ void gemm_tile_mma(
    const float* __restrict__ A, const float* __restrict__ BT,
    float* __restrict__ C, int ldc, int m0, int n0bt, int c0)
{
    __shared__ uint32_t sA[128 * AST];
    __shared__ uint32_t sB[128 * AST];

    const int tid  = threadIdx.x;
    const int lane = tid & 31;
    const int wid  = tid >> 5;
    const int wm   = wid >> 1;          // 0..3  (32-row slice)
    const int wn   = wid & 1;           // 0..1  (64-col slice)
    const int g    = lane >> 2;         // 0..7
    const int tg   = lane & 3;          // 0..3

    float acc[2][8][4];
#pragma unroll
    for (int mi = 0; mi < 2; mi++)
#pragma unroll
        for (int nt = 0; nt < 8; nt++)
#pragma unroll
            for (int j = 0; j < 4; j++) acc[mi][nt][j] = 0.0f;

    for (int k0 = 0; k0 < EMB; k0 += 32) {
        // stage 128x32 A and B chunks, tf32-rounded
#pragma unroll
        for (int t = 0; t < 4; t++) {
            int idx = tid + t * 256;
            int row = idx >> 3;
            int q   = (idx & 7) * 4;
            float4 av = *reinterpret_cast<const float4*>(&A[(size_t)(m0 + row) * EMB + k0 + q]);
            uint32_t* da = &sA[row * AST + q];
            da[0] = f2tf32(av.x); da[1] = f2tf32(av.y); da[2] = f2tf32(av.z); da[3] = f2tf32(av.w);
            float4 bv = *reinterpret_cast<const float4*>(&BT[(size_t)(n0bt + row) * EMB + k0 + q]);
            uint32_t* db = &sB[row * AST + q];
            db[0] = f2tf32(bv.x); db[1] = f2tf32(bv.y); db[2] = f2tf32(bv.z); db[3] = f2tf32(bv.w);
        }
        __syncthreads();

#pragma unroll
        for (int kc = 0; kc < 4; kc++) {
            const int kk = kc * 8;
            uint32_t a[2][4];
#pragma unroll
            for (int mi = 0; mi < 2; mi++) {
                int r = wm * 32 + mi * 16;
                a[mi][0] = sA[(r + g) * AST + kk + tg];
                a[mi][1] = sA[(r + g + 8) * AST + kk + tg];
                a[mi][2] = sA[(r + g) * AST + kk + tg + 4];
                a[mi][3] = sA[(r + g + 8) * AST + kk + tg + 4];
            }
#pragma unroll
            for (int nt = 0; nt < 8; nt++) {
                int n = wn * 64 + nt * 8;
                uint32_t b[2];
                b[0] = sB[(n + g) * AST + kk + tg];
                b[1] = sB[(n + g) * AST + kk + tg + 4];
                mma_tf32(acc[0][nt], a[0], b);
                mma_tf32(acc[1][nt], a[1], b);
            }
        }
        __syncthreads();
    }

    // epilogue
#pragma unroll
    for (int mi = 0; mi < 2; mi++) {
        int r0 = m0 + wm * 32 + mi * 16 + g;
#pragma unroll
        for (int nt = 0; nt < 8; nt++) {
            int col = c0 + wn * 64 + nt * 8 + 2 * tg;
            *reinterpret_cast<float2*>(&C[(size_t)r0 * ldc + col])       = make_float2(acc[mi][nt][0], acc[mi][nt][1]);
            *reinterpret_cast<float2*>(&C[(size_t)(r0 + 8) * ldc + col]) = make_float2(acc[mi][nt][2], acc[mi][nt][3]);
        }
    }
}

// grid (12, 32): 8 Q col-tiles, 2 K, 2 V
__global__ __launch_bounds__(256) void qkv_mma(const float* __restrict__ X) {
    int nb = blockIdx.x;
    float* C; int ldc, c0;
    if (nb < 8)       { C = g_Q; ldc = EMB; c0 = nb * 128; }
    else if (nb < 10) { C = g_K; ldc = KVW; c0 = (nb - 8) * 128; }
    else              { C = g_V; ldc = KVW; c0 = (nb - 10) * 128; }
    gemm_tile_mma(X, g_WT, C, ldc, blockIdx.y * 128, nb * 128, c0);
}

// grid (8, 32)
__global__ __launch_bounds__(256) void oproj_mma(float* __restrict__ out) {
    gemm_tile_mma(g_O, g_WoT, out, EMB, blockIdx.y * 128, blockIdx.x * 128, blockIdx.x * 128);
}

// ================= flash attention, tf32 mma =================================
// 64x64 tiles, 128 threads (4 warps x 16 q-rows). Strides chosen for lane-unique
// banks: Q/P row-pattern -> 68; K/V col-pattern -> 72.
#define QST 68
#define KST 72
#define FA_SMEM ((2 * 64 * QST + 2 * 64 * KST) * 4)   // 71680 B

__global__ __launch_bounds__(128) void flash_mma()
{
    extern __shared__ uint32_t sm[];
    uint32_t* Qs = sm;                  // [64][68]
    uint32_t* Ps = Qs + 64 * QST;       // [64][68]
    uint32_t* Ks = Ps + 64 * QST;       // [64][72]
    uint32_t* Vs = Ks + 64 * KST;       // [64][72]

    const int tid  = threadIdx.x;
    const int lane = tid & 31;
    const int w    = tid >> 5;          // warp 0..3 -> q rows w*16..+15
    const int g    = lane >> 2;
    const int tg   = lane & 3;
    const int w16  = w * 16;

    const int qb  = blockIdx.x;
    const int gh  = blockIdx.y;
    const int grp = gh & 1;
    const int h   = gh >> 1;
    const int kvh = h >> 2;

    const float* Qp = g_Q + grp * EMB + h * HD;
    const float* Kp = g_K + grp * KVW + kvh * HD;
    const float* Vp = g_V + grp * KVW + kvh * HD;
    float*       Op = g_O + grp * EMB + h * HD;

    const int q0 = qb * 64;
    const float scale = 0.125f;

    // stage Q (tf32)
#pragma unroll
    for (int p = 0; p < 8; p++) {
        int idx = tid + p * 128;
        int row = idx >> 4;
        int c   = (idx & 15) * 4;
        float4 qv = *reinterpret_cast<const float4*>(&Qp[(size_t)(q0 + row) * ROWQ + c]);
        uint32_t* d = &Qs[row * QST + c];
        d[0] = f2tf32(qv.x); d[1] = f2tf32(qv.y); d[2] = f2tf32(qv.z); d[3] = f2tf32(qv.w);
    }

    float m_i[2] = {-1e30f, -1e30f};
    float l_i[2] = {0.0f, 0.0f};
    float o[8][4];
#pragma unroll
    for (int nt = 0; nt < 8; nt++)
#pragma unroll
        for (int j = 0; j < 4; j++) o[nt][j] = 0.0f;

    __syncthreads();

    for (int kb = 0; kb <= qb; kb++) {
        const int kn = kb * 64;
        // stage K, V (tf32)
#pragma unroll
        for (int p = 0; p < 8; p++) {
            int idx = tid + p * 128;
            int row = idx >> 4;
            int c   = (idx & 15) * 4;
            float4 kv = *reinterpret_cast<const float4*>(&Kp[(size_t)(kn + row) * ROWK + c]);
            uint32_t* dk = &Ks[row * KST + c];
            dk[0] = f2tf32(kv.x); dk[1] = f2tf32(kv.y); dk[2] = f2tf32(kv.z); dk[3] = f2tf32(kv.w);
            float4 vv = *reinterpret_cast<const float4*>(&Vp[(size_t)(kn + row) * ROWK + c]);
            uint32_t* dv = &Vs[row * KST + c];
            dv[0] = f2tf32(vv.x); dv[1] = f2tf32(vv.y); dv[2] = f2tf32(vv.z); dv[3] = f2tf32(vv.w);
        }
        __syncthreads();

        // S = Q K^T  (A = Q rows w16..+15, B[k=d][n=kpos] = K[n][k])
        float s[8][4];
#pragma unroll
        for (int nt = 0; nt < 8; nt++)
#pragma unroll
            for (int j = 0; j < 4; j++) s[nt][j] = 0.0f;

#pragma unroll
        for (int kc = 0; kc < 8; kc++) {
            const int kk = kc * 8;
            uint32_t a[4];
            a[0] = Qs[(w16 + g) * QST + kk + tg];
            a[1] = Qs[(w16 + g + 8) * QST + kk + tg];
            a[2] = Qs[(w16 + g) * QST + kk + tg + 4];
            a[3] = Qs[(w16 + g + 8) * QST + kk + tg + 4];
#pragma unroll
            for (int nt = 0; nt < 8; nt++) {
                uint32_t b[2];
                b[0] = Ks[(nt * 8 + g) * KST + kk + tg];
                b[1] = Ks[(nt * 8 + g) * KST + kk + tg + 4];
                mma_tf32(s[nt], a, b);
            }
        }

        // online softmax on fragments: thread owns rows r0 = q0+w16+g, r1 = r0+8
        const bool diag = (kb == qb);
        const int r0 = q0 + w16 + g;
        const int r1 = r0 + 8;
        float mx0 = -1e30f, mx1 = -1e30f;
#pragma unroll
        for (int nt = 0; nt < 8; nt++) {
            int c0 = kn + nt * 8 + 2 * tg;
            float v0 = s[nt][0] * scale, v1 = s[nt][1] * scale;
            float v2 = s[nt][2] * scale, v3 = s[nt][3] * scale;
            if (diag) {
                if (c0 > r0)     v0 = -1e30f;
                if (c0 + 1 > r0) v1 = -1e30f;
                if (c0 > r1)     v2 = -1e30f;
                if (c0 + 1 > r1) v3 = -1e30f;
            }
            s[nt][0] = v0; s[nt][1] = v1; s[nt][2] = v2; s[nt][3] = v3;
            mx0 = fmaxf(mx0, fmaxf(v0, v1));
            mx1 = fmaxf(mx1, fmaxf(v2, v3));
        }
        mx0 = fmaxf(mx0, __shfl_xor_sync(0xffffffffu, mx0, 1));
        mx0 = fmaxf(mx0, __shfl_xor_sync(0xffffffffu, mx0, 2));
        mx1 = fmaxf(mx1, __shfl_xor_sync(0xffffffffu, mx1, 1));
        mx1 = fmaxf(mx1, __shfl_xor_sync(0xffffffffu, mx1, 2));

        float mn0 = fmaxf(m_i[0], mx0), mn1 = fmaxf(m_i[1], mx1);
        float al0 = __expf(m_i[0] - mn0), al1 = __expf(m_i[1] - mn1);
        float ps0 = 0.0f, ps1 = 0.0f;
#pragma unroll
        for (int nt = 0; nt < 8; nt++) {
            float p0 = __expf(s[nt][0] - mn0);
            float p1 = __expf(s[nt][1] - mn0);
            float p2 = __expf(s[nt][2] - mn1);
            float p3 = __expf(s[nt][3] - mn1);
            ps0 += p0 + p1; ps1 += p2 + p3;
            int cc = nt * 8 + 2 * tg;
            Ps[(w16 + g) * QST + cc]     = f2tf32(p0);
            Ps[(w16 + g) * QST + cc + 1] = f2tf32(p1);
            Ps[(w16 + g + 8) * QST + cc]     = f2tf32(p2);
            Ps[(w16 + g + 8) * QST + cc + 1] = f2tf32(p3);
            o[nt][0] *= al0; o[nt][1] *= al0;
            o[nt][2] *= al1; o[nt][3] *= al1;
        }
        ps0 += __shfl_xor_sync(0xffffffffu, ps0, 1);
        ps0 += __shfl_xor_sync(0xffffffffu, ps0, 2);
        ps1 += __shfl_xor_sync(0xffffffffu, ps1, 1);
        ps1 += __shfl_xor_sync(0xffffffffu, ps1, 2);
        l_i[0] = l_i[0] * al0 + ps0;
        l_i[1] = l_i[1] * al1 + ps1;
        m_i[0] = mn0; m_i[1] = mn1;
        __syncwarp();

        // O += P V  (A = P rows w16..+15, B[k=kpos][n=d] = V row-major)
#pragma unroll
        for (int kc = 0; kc < 8; kc++) {
            const int kk = kc * 8;
            uint32_t a[4];
            a[0] = Ps[(w16 + g) * QST + kk + tg];
            a[1] = Ps[(w16 + g + 8) * QST + kk + tg];
            a[2] = Ps[(w16 + g) * QST + kk + tg + 4];
            a[3] = Ps[(w16 + g + 8) * QST + kk + tg + 4];
#pragma unroll
            for (int nt = 0; nt < 8; nt++) {
                uint32_t b[2];
                b[0] = Vs[(kk + tg) * KST + nt * 8 + g];
                b[1] = Vs[(kk + tg + 4) * KST + nt * 8 + g];
                mma_tf32(o[nt], a, b);
            }
        }
        __syncthreads();
    }

    // epilogue: normalize and write O
    const float inv0 = 1.0f / l_i[0];
    const float inv1 = 1.0f / l_i[1];
    const size_t row0 = (size_t)(q0 + w16 + g) * ROWQ;
    const size_t row1 = row0 + 8 * ROWQ;
#pragma unroll
    for (int nt = 0; nt < 8; nt++) {
        int cc = nt * 8 + 2 * tg;
        *reinterpret_cast<float2*>(&Op[row0 + cc]) = make_float2(o[nt][0] * inv0, o[nt][1] * inv0);
        *reinterpret_cast<float2*>(&Op[row1 + cc]) = make_float2(o[nt][2] * inv1, o[nt][3] * inv1);
    }
}

// ================= launch =====================================================
extern "C" void kernel_launch(void* const* d_in, const int* in_sizes, int n_in,
                              void* d_out, int out_size)
{
    const float* x  = (const float*)d_in[0];
    const float* Wq = (const float*)d_in[1];
    const float* Wk = (const float*)d_in[2];
    const float* Wv = (const float*)d_in[3];
    const float* Wo = (const float*)d_in[4];
    float* out = (float*)d_out;

    cudaFuncSetAttribute(flash_mma, cudaFuncAttributeMaxDynamicSharedMemorySize, FA_SMEM);

    float* wt = nullptr; float* wot = nullptr;
    cudaGetSymbolAddress((void**)&wt,  g_WT);
    cudaGetSymbolAddress((void**)&wot, g_WoT);

    transpose32<<<dim3(32, 32), dim3(32, 32)>>>(Wq, wt,                              EMB, EMB);
    transpose32<<<dim3(8,  32), dim3(32, 32)>>>(Wk, wt + (size_t)EMB * EMB,          KVW, EMB);
    transpose32<<<dim3(8,  32), dim3(32, 32)>>>(Wv, wt + (size_t)(EMB + KVW) * EMB,  KVW, EMB);
    transpose32<<<dim3(32, 32), dim3(32, 32)>>>(Wo, wot,                             EMB, EMB);

    qkv_mma<<<dim3(12, 32), 256>>>(x);
    flash_mma<<<dim3(32, 32), 128, FA_SMEM>>>();
    oproj_mma<<<dim3(8, 32), 256>>>(out);
}

// round 4
// speedup vs baseline: 3.3807x; 1.9126x over previous
#include <cuda_runtime.h>
#include <cstdint>
#include <math.h>

#define S_LEN  2048
#define G_GRP  2
#define EMB    1024
#define NH     16
#define NKV    4
#define HD     64
#define MROWS  (S_LEN * G_GRP)      // 4096
#define KVW    (NKV * HD)           // 256
#define ROWQ   (G_GRP * EMB)        // 2048
#define ROWK   (G_GRP * KVW)        // 512

// ---------------- scratch (no allocation allowed) ----------------
__device__ float g_X[MROWS * EMB];              // tf32-rounded input
__device__ float g_Q[MROWS * EMB];              // tf32-rounded (scaled at flash stage)
__device__ float g_K[MROWS * KVW];              // tf32-rounded
__device__ float g_V[MROWS * KVW];              // tf32-rounded
__device__ float g_O[MROWS * EMB];              // tf32-rounded
__device__ float g_WT[(EMB + 2 * KVW) * EMB];   // [1536][1024] transposed + rounded
__device__ float g_WoT[EMB * EMB];              // transposed + rounded

// ================= helpers =================
__device__ __forceinline__ uint32_t smem_u32(const void* p) {
    uint32_t a;
    asm("{ .reg .u64 t; cvta.to.shared.u64 t, %1; cvt.u32.u64 %0, t; }" : "=r"(a) : "l"(p));
    return a;
}
__device__ __forceinline__ uint32_t f2tf32(float x) {
    uint32_t r;
    asm("cvt.rna.tf32.f32 %0, %1;" : "=r"(r) : "f"(x));
    return r;
}
__device__ __forceinline__ float rtf(float x) { return __uint_as_float(f2tf32(x)); }

__device__ __forceinline__ void mma_tf32(float c[4], const uint32_t a[4], const uint32_t b[2]) {
    asm volatile(
        "mma.sync.aligned.m16n8k8.row.col.f32.tf32.tf32.f32 "
        "{%0,%1,%2,%3}, {%4,%5,%6,%7}, {%8,%9}, {%0,%1,%2,%3};"
        : "+f"(c[0]), "+f"(c[1]), "+f"(c[2]), "+f"(c[3])
        : "r"(a[0]), "r"(a[1]), "r"(a[2]), "r"(a[3]), "r"(b[0]), "r"(b[1]));
}

__device__ __forceinline__ void cpa16(uint32_t dst, const float* src) {
    asm volatile("cp.async.cg.shared.global [%0], [%1], 16;" :: "r"(dst), "l"(src));
}
__device__ __forceinline__ void cpa_commit() { asm volatile("cp.async.commit_group;"); }
template <int N>
__device__ __forceinline__ void cpa_wait() { asm volatile("cp.async.wait_group %0;" :: "n"(N)); }

// ================= producer-side rounding kernels =================
__global__ __launch_bounds__(1024) void transpose32(const float* __restrict__ W,
                                                    float* __restrict__ WT, int N, int K) {
    __shared__ float t[32][33];
    int n = blockIdx.x * 32 + threadIdx.x;
    int k = blockIdx.y * 32 + threadIdx.y;
    t[threadIdx.y][threadIdx.x] = rtf(W[(size_t)k * N + n]);
    __syncthreads();
    int n2 = blockIdx.x * 32 + threadIdx.y;
    int k2 = blockIdx.y * 32 + threadIdx.x;
    WT[(size_t)n2 * K + k2] = t[threadIdx.x][threadIdx.y];
}

__global__ __launch_bounds__(512) void round_x(const float* __restrict__ x) {
    int i = blockIdx.x * 512 + threadIdx.x;
    float4 v = reinterpret_cast<const float4*>(x)[i];
    float4 r = make_float4(rtf(v.x), rtf(v.y), rtf(v.z), rtf(v.w));
    reinterpret_cast<float4*>(g_X)[i] = r;
}

// ================= tf32 mma GEMM, cp.async double-buffered ====================
// A: [M][1024] row-major (pre-rounded); BT: [N][1024] row-major (pre-rounded).
#define AST 36
#define ABUF (128 * AST)                 // one A or B chunk, uint32
#define GEMM_SMEM (4 * ABUF * 4)         // 73728 B

template <bool ROUND>
__device__ __forceinline__ void gemm_tile(
    const float* __restrict__ A, const float* __restrict__ BT,
    float* __restrict__ C, int ldc, int m0, int n0bt, int c0)
{
    extern __shared__ uint32_t dsm[];
    const uint32_t sb = smem_u32(dsm);

    const int tid  = threadIdx.x;
    const int lane = tid & 31;
    const int wid  = tid >> 5;
    const int wm   = wid >> 1;
    const int wn   = wid & 1;
    const int g    = lane >> 2;
    const int tg   = lane & 3;

    float acc[2][8][4];
#pragma unroll
    for (int mi = 0; mi < 2; mi++)
#pragma unroll
        for (int nt = 0; nt < 8; nt++)
#pragma unroll
            for (int j = 0; j < 4; j++) acc[mi][nt][j] = 0.0f;

    const int row = tid >> 3;           // 0..31 step over 4 iters below
    const int q   = (tid & 7) * 4;

    // stage chunk c into buffer buf (cp.async, raw pre-rounded bits)
    auto stage = [&](int c, int buf) {
        const int k0 = c * 32;
        const uint32_t aBase = sb + (uint32_t)(2 * buf) * ABUF * 4;
        const uint32_t bBase = aBase + ABUF * 4;
#pragma unroll
        for (int t = 0; t < 4; t++) {
            int r = row + t * 32;
            cpa16(aBase + (uint32_t)(r * AST + q) * 4, &A [(size_t)(m0 + r) * EMB + k0 + q]);
            cpa16(bBase + (uint32_t)(r * AST + q) * 4, &BT[(size_t)(n0bt + r) * EMB + k0 + q]);
        }
    };

    stage(0, 0);
    cpa_commit();

    for (int c = 0; c < 32; c++) {
        if (c < 31) {
            stage(c + 1, (c + 1) & 1);
            cpa_commit();
            cpa_wait<1>();
        } else {
            cpa_wait<0>();
        }
        __syncthreads();

        const uint32_t* sA = dsm + (size_t)(2 * (c & 1)) * ABUF;
        const uint32_t* sB = sA + ABUF;
#pragma unroll
        for (int kc = 0; kc < 4; kc++) {
            const int kk = kc * 8;
            uint32_t a[2][4];
#pragma unroll
            for (int mi = 0; mi < 2; mi++) {
                int r = wm * 32 + mi * 16;
                a[mi][0] = sA[(r + g) * AST + kk + tg];
                a[mi][1] = sA[(r + g + 8) * AST + kk + tg];
                a[mi][2] = sA[(r + g) * AST + kk + tg + 4];
                a[mi][3] = sA[(r + g + 8) * AST + kk + tg + 4];
            }
#pragma unroll
            for (int nt = 0; nt < 8; nt++) {
                int n = wn * 64 + nt * 8;
                uint32_t b[2];
                b[0] = sB[(n + g) * AST + kk + tg];
                b[1] = sB[(n + g) * AST + kk + tg + 4];
                mma_tf32(acc[0][nt], a[0], b);
                mma_tf32(acc[1][nt], a[1], b);
            }
        }
        __syncthreads();
    }

#pragma unroll
    for (int mi = 0; mi < 2; mi++) {
        int r0 = m0 + wm * 32 + mi * 16 + g;
#pragma unroll
        for (int nt = 0; nt < 8; nt++) {
            int col = c0 + wn * 64 + nt * 8 + 2 * tg;
            float2 v0, v1;
            if (ROUND) {
                v0 = make_float2(rtf(acc[mi][nt][0]), rtf(acc[mi][nt][1]));
                v1 = make_float2(rtf(acc[mi][nt][2]), rtf(acc[mi][nt][3]));
            } else {
                v0 = make_float2(acc[mi][nt][0], acc[mi][nt][1]);
                v1 = make_float2(acc[mi][nt][2], acc[mi][nt][3]);
            }
            *reinterpret_cast<float2*>(&C[(size_t)r0 * ldc + col])       = v0;
            *reinterpret_cast<float2*>(&C[(size_t)(r0 + 8) * ldc + col]) = v1;
        }
    }
}

__global__ __launch_bounds__(256) void qkv_mma() {
    int nb = blockIdx.x;
    float* C; int ldc, c0;
    if (nb < 8)       { C = g_Q; ldc = EMB; c0 = nb * 128; }
    else if (nb < 10) { C = g_K; ldc = KVW; c0 = (nb - 8) * 128; }
    else              { C = g_V; ldc = KVW; c0 = (nb - 10) * 128; }
    gemm_tile<true>(g_X, g_WT, C, ldc, blockIdx.y * 128, nb * 128, c0);
}

__global__ __launch_bounds__(256) void oproj_mma(float* __restrict__ out) {
    gemm_tile<false>(g_O, g_WoT, out, EMB, blockIdx.y * 128, blockIdx.x * 128, blockIdx.x * 128);
}

// ================= flash attention, tf32 mma, cp.async K/V ====================
#define QST 68
#define KST 72
#define PS_SZ (64 * QST)                 // 4352 floats
#define KV_SZ (64 * KST)                 // 4608 floats
#define FA_SMEM ((PS_SZ + 4 * KV_SZ) * 4)   // 91136 B

__global__ __launch_bounds__(128) void flash_mma()
{
    extern __shared__ float fsm[];
    float* Ps  = fsm;                        // [64][68], also Q staging
    float* KsB[2] = { fsm + PS_SZ,            fsm + PS_SZ + KV_SZ };
    float* VsB[2] = { fsm + PS_SZ + 2 * KV_SZ, fsm + PS_SZ + 3 * KV_SZ };
    const uint32_t sb = smem_u32(fsm);

    const int tid  = threadIdx.x;
    const int lane = tid & 31;
    const int w    = tid >> 5;
    const int g    = lane >> 2;
    const int tg   = lane & 3;
    const int w16  = w * 16;

    const int qb  = gridDim.x - 1 - blockIdx.x;   // longest CTAs first
    const int gh  = blockIdx.y;
    const int grp = gh & 1;
    const int h   = gh >> 1;
    const int kvh = h >> 2;

    const float* Qp = g_Q + grp * EMB + h * HD;
    const float* Kp = g_K + grp * KVW + kvh * HD;
    const float* Vp = g_V + grp * KVW + kvh * HD;
    float*       Op = g_O + grp * EMB + h * HD;

    const int q0 = qb * 64;

    // ---- stage Q scaled by 1/8 (exact exponent shift on tf32 values) ----
    {
        const int row = tid >> 4;
        const int c   = (tid & 15) * 4;
#pragma unroll
        for (int p = 0; p < 8; p++) {
            int r = row + p * 8;
            float4 qv = *reinterpret_cast<const float4*>(&Qp[(size_t)(q0 + r) * ROWQ + c]);
            float* d = &Ps[r * QST + c];
            d[0] = qv.x * 0.125f; d[1] = qv.y * 0.125f;
            d[2] = qv.z * 0.125f; d[3] = qv.w * 0.125f;
        }
    }
    __syncthreads();

    // ---- hoist Q fragments into registers ----
    uint32_t aq[8][4];
#pragma unroll
    for (int kc = 0; kc < 8; kc++) {
        const int kk = kc * 8;
        aq[kc][0] = __float_as_uint(Ps[(w16 + g) * QST + kk + tg]);
        aq[kc][1] = __float_as_uint(Ps[(w16 + g + 8) * QST + kk + tg]);
        aq[kc][2] = __float_as_uint(Ps[(w16 + g) * QST + kk + tg + 4]);
        aq[kc][3] = __float_as_uint(Ps[(w16 + g + 8) * QST + kk + tg + 4]);
    }
    __syncthreads();   // Ps free for P reuse (P rows are warp-private afterwards)

    // ---- K/V cp.async staging ----
    const int srow = tid >> 4;
    const int sq   = (tid & 15) * 4;
    auto stage_kv = [&](int kb, int buf) {
        const int kn = kb * 64;
        const uint32_t kBase = sb + (uint32_t)(PS_SZ + buf * KV_SZ) * 4;
        const uint32_t vBase = sb + (uint32_t)(PS_SZ + (2 + buf) * KV_SZ) * 4;
#pragma unroll
        for (int p = 0; p < 8; p++) {
            int r = srow + p * 8;
            cpa16(kBase + (uint32_t)(r * KST + sq) * 4, &Kp[(size_t)(kn + r) * ROWK + sq]);
            cpa16(vBase + (uint32_t)(r * KST + sq) * 4, &Vp[(size_t)(kn + r) * ROWK + sq]);
        }
    };

    float m_i[2] = {-1e30f, -1e30f};
    float l_i[2] = {0.0f, 0.0f};
    float o[8][4];
#pragma unroll
    for (int nt = 0; nt < 8; nt++)
#pragma unroll
        for (int j = 0; j < 4; j++) o[nt][j] = 0.0f;

    stage_kv(0, 0);
    cpa_commit();

    for (int kb = 0; kb <= qb; kb++) {
        const int kn  = kb * 64;
        const int buf = kb & 1;
        if (kb < qb) {
            stage_kv(kb + 1, buf ^ 1);
            cpa_commit();
            cpa_wait<1>();
        } else {
            cpa_wait<0>();
        }
        __syncthreads();

        const uint32_t* Ks = reinterpret_cast<const uint32_t*>(KsB[buf]);
        const uint32_t* Vs = reinterpret_cast<const uint32_t*>(VsB[buf]);

        // S = (Q/8) K^T
        float s[8][4];
#pragma unroll
        for (int nt = 0; nt < 8; nt++)
#pragma unroll
            for (int j = 0; j < 4; j++) s[nt][j] = 0.0f;

#pragma unroll
        for (int kc = 0; kc < 8; kc++) {
            const int kk = kc * 8;
#pragma unroll
            for (int nt = 0; nt < 8; nt++) {
                uint32_t b[2];
                b[0] = Ks[(nt * 8 + g) * KST + kk + tg];
                b[1] = Ks[(nt * 8 + g) * KST + kk + tg + 4];
                mma_tf32(s[nt], aq[kc], b);
            }
        }

        // online softmax (rows r0, r1 per thread)
        const bool diag = (kn + 63 >= q0);
        const int r0 = q0 + w16 + g;
        const int r1 = r0 + 8;
        float mx0 = -1e30f, mx1 = -1e30f;
#pragma unroll
        for (int nt = 0; nt < 8; nt++) {
            int cc = kn + nt * 8 + 2 * tg;
            float v0 = s[nt][0], v1 = s[nt][1], v2 = s[nt][2], v3 = s[nt][3];
            if (diag) {
                if (cc > r0)     v0 = -1e30f;
                if (cc + 1 > r0) v1 = -1e30f;
                if (cc > r1)     v2 = -1e30f;
                if (cc + 1 > r1) v3 = -1e30f;
            }
            s[nt][0] = v0; s[nt][1] = v1; s[nt][2] = v2; s[nt][3] = v3;
            mx0 = fmaxf(mx0, fmaxf(v0, v1));
            mx1 = fmaxf(mx1, fmaxf(v2, v3));
        }
        mx0 = fmaxf(mx0, __shfl_xor_sync(0xffffffffu, mx0, 1));
        mx0 = fmaxf(mx0, __shfl_xor_sync(0xffffffffu, mx0, 2));
        mx1 = fmaxf(mx1, __shfl_xor_sync(0xffffffffu, mx1, 1));
        mx1 = fmaxf(mx1, __shfl_xor_sync(0xffffffffu, mx1, 2));

        float mn0 = fmaxf(m_i[0], mx0), mn1 = fmaxf(m_i[1], mx1);
        float al0 = __expf(m_i[0] - mn0), al1 = __expf(m_i[1] - mn1);
        float ps0 = 0.0f, ps1 = 0.0f;
#pragma unroll
        for (int nt = 0; nt < 8; nt++) {
            float p0 = __expf(s[nt][0] - mn0);
            float p1 = __expf(s[nt][1] - mn0);
            float p2 = __expf(s[nt][2] - mn1);
            float p3 = __expf(s[nt][3] - mn1);
            ps0 += p0 + p1; ps1 += p2 + p3;
            int cc = nt * 8 + 2 * tg;
            Ps[(w16 + g) * QST + cc]         = __uint_as_float(f2tf32(p0));
            Ps[(w16 + g) * QST + cc + 1]     = __uint_as_float(f2tf32(p1));
            Ps[(w16 + g + 8) * QST + cc]     = __uint_as_float(f2tf32(p2));
            Ps[(w16 + g + 8) * QST + cc + 1] = __uint_as_float(f2tf32(p3));
            o[nt][0] *= al0; o[nt][1] *= al0;
            o[nt][2] *= al1; o[nt][3] *= al1;
        }
        ps0 += __shfl_xor_sync(0xffffffffu, ps0, 1);
        ps0 += __shfl_xor_sync(0xffffffffu, ps0, 2);
        ps1 += __shfl_xor_sync(0xffffffffu, ps1, 1);
        ps1 += __shfl_xor_sync(0xffffffffu, ps1, 2);
        l_i[0] = l_i[0] * al0 + ps0;
        l_i[1] = l_i[1] * al1 + ps1;
        m_i[0] = mn0; m_i[1] = mn1;
        __syncwarp();

        // O += P V
        const uint32_t* Pu = reinterpret_cast<const uint32_t*>(Ps);
#pragma unroll
        for (int kc = 0; kc < 8; kc++) {
            const int kk = kc * 8;
            uint32_t a[4];
            a[0] = Pu[(w16 + g) * QST + kk + tg];
            a[1] = Pu[(w16 + g + 8) * QST + kk + tg];
            a[2] = Pu[(w16 + g) * QST + kk + tg + 4];
            a[3] = Pu[(w16 + g + 8) * QST + kk + tg + 4];
#pragma unroll
            for (int nt = 0; nt < 8; nt++) {
                uint32_t b[2];
                b[0] = Vs[(kk + tg) * KST + nt * 8 + g];
                b[1] = Vs[(kk + tg + 4) * KST + nt * 8 + g];
                mma_tf32(o[nt], a, b);
            }
        }
        __syncthreads();
    }

    // epilogue: normalize, round (g_O feeds oproj A via cp.async), write
    const float inv0 = 1.0f / l_i[0];
    const float inv1 = 1.0f / l_i[1];
    const size_t row0 = (size_t)(q0 + w16 + g) * ROWQ;
    const size_t row1 = row0 + 8 * ROWQ;
#pragma unroll
    for (int nt = 0; nt < 8; nt++) {
        int cc = nt * 8 + 2 * tg;
        *reinterpret_cast<float2*>(&Op[row0 + cc]) =
            make_float2(rtf(o[nt][0] * inv0), rtf(o[nt][1] * inv0));
        *reinterpret_cast<float2*>(&Op[row1 + cc]) =
            make_float2(rtf(o[nt][2] * inv1), rtf(o[nt][3] * inv1));
    }
}

// ================= launch =====================================================
extern "C" void kernel_launch(void* const* d_in, const int* in_sizes, int n_in,
                              void* d_out, int out_size)
{
    const float* x  = (const float*)d_in[0];
    const float* Wq = (const float*)d_in[1];
    const float* Wk = (const float*)d_in[2];
    const float* Wv = (const float*)d_in[3];
    const float* Wo = (const float*)d_in[4];
    float* out = (float*)d_out;

    cudaFuncSetAttribute(flash_mma, cudaFuncAttributeMaxDynamicSharedMemorySize, FA_SMEM);
    cudaFuncSetAttribute(qkv_mma,   cudaFuncAttributeMaxDynamicSharedMemorySize, GEMM_SMEM);
    cudaFuncSetAttribute(oproj_mma, cudaFuncAttributeMaxDynamicSharedMemorySize, GEMM_SMEM);

    float* wt = nullptr; float* wot = nullptr;
    cudaGetSymbolAddress((void**)&wt,  g_WT);
    cudaGetSymbolAddress((void**)&wot, g_WoT);

    round_x<<<MROWS * EMB / (512 * 4), 512>>>(x);
    transpose32<<<dim3(32, 32), dim3(32, 32)>>>(Wq, wt,                              EMB, EMB);
    transpose32<<<dim3(8,  32), dim3(32, 32)>>>(Wk, wt + (size_t)EMB * EMB,          KVW, EMB);
    transpose32<<<dim3(8,  32), dim3(32, 32)>>>(Wv, wt + (size_t)(EMB + KVW) * EMB,  KVW, EMB);
    transpose32<<<dim3(32, 32), dim3(32, 32)>>>(Wo, wot,                             EMB, EMB);

    qkv_mma<<<dim3(12, 32), 256, GEMM_SMEM>>>();
    flash_mma<<<dim3(32, 32), 128, FA_SMEM>>>();
    oproj_mma<<<dim3(8, 32), 256, GEMM_SMEM>>>(out);
}

// round 5
// speedup vs baseline: 4.5066x; 1.3331x over previous
#include <cuda_runtime.h>
#include <cstdint>
#include <math.h>

#define S_LEN  2048
#define G_GRP  2
#define EMB    1024
#define NH     16
#define NKV    4
#define HD     64
#define MROWS  (S_LEN * G_GRP)      // 4096
#define KVW    (NKV * HD)           // 256
#define ROWQ   (G_GRP * EMB)        // 2048
#define ROWK   (G_GRP * KVW)        // 512

// ---------------- scratch ----------------
__device__ float g_X[MROWS * EMB];
__device__ float g_Q[MROWS * EMB];
__device__ float g_K[MROWS * KVW];
__device__ float g_V[MROWS * KVW];
__device__ float g_O[MROWS * EMB];
__device__ float g_WT[(EMB + 2 * KVW) * EMB];
__device__ float g_WoT[EMB * EMB];

// ================= helpers =================
__device__ __forceinline__ uint32_t smem_u32(const void* p) {
    uint32_t a;
    asm("{ .reg .u64 t; cvta.to.shared.u64 t, %1; cvt.u32.u64 %0, t; }" : "=r"(a) : "l"(p));
    return a;
}
__device__ __forceinline__ uint32_t f2tf32(float x) {
    uint32_t r;
    asm("cvt.rna.tf32.f32 %0, %1;" : "=r"(r) : "f"(x));
    return r;
}
__device__ __forceinline__ float rtf(float x) { return __uint_as_float(f2tf32(x)); }

__device__ __forceinline__ void mma_tf32(float c[4], const uint32_t a[4], const uint32_t b[2]) {
    asm volatile(
        "mma.sync.aligned.m16n8k8.row.col.f32.tf32.tf32.f32 "
        "{%0,%1,%2,%3}, {%4,%5,%6,%7}, {%8,%9}, {%0,%1,%2,%3};"
        : "+f"(c[0]), "+f"(c[1]), "+f"(c[2]), "+f"(c[3])
        : "r"(a[0]), "r"(a[1]), "r"(a[2]), "r"(a[3]), "r"(b[0]), "r"(b[1]));
}

__device__ __forceinline__ void cpa16(uint32_t dst, const float* src) {
    asm volatile("cp.async.cg.shared.global [%0], [%1], 16;" :: "r"(dst), "l"(src));
}
__device__ __forceinline__ void cpa_commit() { asm volatile("cp.async.commit_group;"); }
template <int N>
__device__ __forceinline__ void cpa_wait() { asm volatile("cp.async.wait_group %0;" :: "n"(N)); }

// ================= producer-side prep =================
__global__ __launch_bounds__(1024) void transpose_all(
    const float* __restrict__ Wq, const float* __restrict__ Wk,
    const float* __restrict__ Wv, const float* __restrict__ Wo)
{
    __shared__ float t[32][33];
    const int bx = blockIdx.x;
    const float* W; float* WT; int N; int nb;
    if (bx < 32)      { W = Wq; WT = g_WT;                               N = EMB; nb = bx; }
    else if (bx < 40) { W = Wk; WT = g_WT + (size_t)EMB * EMB;           N = KVW; nb = bx - 32; }
    else if (bx < 48) { W = Wv; WT = g_WT + (size_t)(EMB + KVW) * EMB;   N = KVW; nb = bx - 40; }
    else              { W = Wo; WT = g_WoT;                              N = EMB; nb = bx - 48; }

    int n = nb * 32 + threadIdx.x;
    int k = blockIdx.y * 32 + threadIdx.y;
    t[threadIdx.y][threadIdx.x] = rtf(W[(size_t)k * N + n]);
    __syncthreads();
    int n2 = nb * 32 + threadIdx.y;
    int k2 = blockIdx.y * 32 + threadIdx.x;
    WT[(size_t)n2 * EMB + k2] = t[threadIdx.x][threadIdx.y];
}

__global__ __launch_bounds__(512) void round_x(const float* __restrict__ x) {
    int i = blockIdx.x * 512 + threadIdx.x;
    float4 v = reinterpret_cast<const float4*>(x)[i];
    reinterpret_cast<float4*>(g_X)[i] = make_float4(rtf(v.x), rtf(v.y), rtf(v.z), rtf(v.w));
}

// ================= tf32 mma GEMM: 128x128 CTA tile, 64x64 warp tile ==========
#define AST 36
#define ABUF (128 * AST)
#define GEMM_SMEM (4 * ABUF * 4)     // 73728 B

template <bool ROUND>
__device__ __forceinline__ void gemm_tile(
    const float* __restrict__ A, const float* __restrict__ BT,
    float* __restrict__ C, int ldc, int m0, int n0bt, int c0)
{
    extern __shared__ uint32_t dsm[];
    const uint32_t sb = smem_u32(dsm);

    const int tid  = threadIdx.x;      // 0..127
    const int lane = tid & 31;
    const int wid  = tid >> 5;         // 0..3
    const int wm   = wid >> 1;         // 0..1 -> 64-row slice
    const int wn   = wid & 1;          // 0..1 -> 64-col slice
    const int g    = lane >> 2;
    const int tg   = lane & 3;

    float acc[4][8][4];
#pragma unroll
    for (int mi = 0; mi < 4; mi++)
#pragma unroll
        for (int nt = 0; nt < 8; nt++)
#pragma unroll
            for (int j = 0; j < 4; j++) acc[mi][nt][j] = 0.0f;

    const int row = tid >> 3;          // 0..15
    const int q   = (tid & 7) * 4;

    auto stage = [&](int c, int buf) {
        const int k0 = c * 32;
        const uint32_t aBase = sb + (uint32_t)(2 * buf) * ABUF * 4;
        const uint32_t bBase = aBase + ABUF * 4;
#pragma unroll
        for (int t = 0; t < 8; t++) {
            int r = row + t * 16;
            cpa16(aBase + (uint32_t)(r * AST + q) * 4, &A [(size_t)(m0 + r) * EMB + k0 + q]);
            cpa16(bBase + (uint32_t)(r * AST + q) * 4, &BT[(size_t)(n0bt + r) * EMB + k0 + q]);
        }
    };

    stage(0, 0);
    cpa_commit();

    for (int c = 0; c < 32; c++) {
        if (c < 31) {
            stage(c + 1, (c + 1) & 1);
            cpa_commit();
            cpa_wait<1>();
        } else {
            cpa_wait<0>();
        }
        __syncthreads();

        const uint32_t* sA = dsm + (size_t)(2 * (c & 1)) * ABUF;
        const uint32_t* sB = sA + ABUF;
#pragma unroll
        for (int kc = 0; kc < 4; kc++) {
            const int kk = kc * 8;
            uint32_t a[4][4];
#pragma unroll
            for (int mi = 0; mi < 4; mi++) {
                int r = wm * 64 + mi * 16;
                a[mi][0] = sA[(r + g) * AST + kk + tg];
                a[mi][1] = sA[(r + g + 8) * AST + kk + tg];
                a[mi][2] = sA[(r + g) * AST + kk + tg + 4];
                a[mi][3] = sA[(r + g + 8) * AST + kk + tg + 4];
            }
#pragma unroll
            for (int nt = 0; nt < 8; nt++) {
                int n = wn * 64 + nt * 8;
                uint32_t b[2];
                b[0] = sB[(n + g) * AST + kk + tg];
                b[1] = sB[(n + g) * AST + kk + tg + 4];
                mma_tf32(acc[0][nt], a[0], b);
                mma_tf32(acc[1][nt], a[1], b);
                mma_tf32(acc[2][nt], a[2], b);
                mma_tf32(acc[3][nt], a[3], b);
            }
        }
        __syncthreads();
    }

#pragma unroll
    for (int mi = 0; mi < 4; mi++) {
        int r0 = m0 + wm * 64 + mi * 16 + g;
#pragma unroll
        for (int nt = 0; nt < 8; nt++) {
            int col = c0 + wn * 64 + nt * 8 + 2 * tg;
            float2 v0, v1;
            if (ROUND) {
                v0 = make_float2(rtf(acc[mi][nt][0]), rtf(acc[mi][nt][1]));
                v1 = make_float2(rtf(acc[mi][nt][2]), rtf(acc[mi][nt][3]));
            } else {
                v0 = make_float2(acc[mi][nt][0], acc[mi][nt][1]);
                v1 = make_float2(acc[mi][nt][2], acc[mi][nt][3]);
            }
            *reinterpret_cast<float2*>(&C[(size_t)r0 * ldc + col])       = v0;
            *reinterpret_cast<float2*>(&C[(size_t)(r0 + 8) * ldc + col]) = v1;
        }
    }
}

__global__ __launch_bounds__(128) void qkv_mma() {
    int nb = blockIdx.x;
    float* C; int ldc, c0;
    if (nb < 8)       { C = g_Q; ldc = EMB; c0 = nb * 128; }
    else if (nb < 10) { C = g_K; ldc = KVW; c0 = (nb - 8) * 128; }
    else              { C = g_V; ldc = KVW; c0 = (nb - 10) * 128; }
    gemm_tile<true>(g_X, g_WT, C, ldc, blockIdx.y * 128, nb * 128, c0);
}

__global__ __launch_bounds__(128) void oproj_mma(float* __restrict__ out) {
    gemm_tile<false>(g_O, g_WoT, out, EMB, blockIdx.y * 128, blockIdx.x * 128, blockIdx.x * 128);
}

// ================= flash attention: BM=128, 4 warps x 32 rows ================
#define QST  68                       // Q/P stride (lane-unique: 68 % 32 == 4)
#define KSTK 68                       // K stride (row-pattern g -> needs ≡4 mod 32)
#define KSTV 72                       // V stride (row-pattern tg -> needs ≡8 mod 32)
#define PS_SZ (128 * QST)             // 8704 floats
#define KBUF  (64 * KSTK)             // 4352 floats
#define VBUF  (64 * KSTV)             // 4608 floats
#define FA_SMEM ((PS_SZ + 2 * KBUF + 2 * VBUF) * 4)   // 106496 B

__global__ __launch_bounds__(128) void flash_mma()
{
    extern __shared__ float fsm[];
    float* Ps = fsm;                                   // [128][QST] (Q staging, then P)
    float* Kb0 = fsm + PS_SZ;
    float* Kb1 = Kb0 + KBUF;
    float* Vb0 = Kb1 + KBUF;
    float* Vb1 = Vb0 + VBUF;
    const uint32_t sb = smem_u32(fsm);

    const int tid  = threadIdx.x;
    const int lane = tid & 31;
    const int w    = tid >> 5;         // 0..3
    const int g    = lane >> 2;
    const int tg   = lane & 3;
    const int wr   = w * 32;           // warp's 32 q-rows

    const int gh  = blockIdx.x;                    // 0..31
    const int qb  = (int)gridDim.y - 1 - blockIdx.y;   // descending work first
    const int grp = gh & 1;
    const int h   = gh >> 1;
    const int kvh = h >> 2;

    const float* Qp = g_Q + grp * EMB + h * HD;
    const float* Kp = g_K + grp * KVW + kvh * HD;
    const float* Vp = g_V + grp * KVW + kvh * HD;
    float*       Op = g_O + grp * EMB + h * HD;

    const int q0 = qb * 128;

    // ---- stage Q (x 1/8, exact) into Ps ----
    {
        const int row = tid >> 4;
        const int c   = (tid & 15) * 4;
#pragma unroll
        for (int p = 0; p < 16; p++) {
            int r = row + p * 8;
            float4 qv = *reinterpret_cast<const float4*>(&Qp[(size_t)(q0 + r) * ROWQ + c]);
            float* d = &Ps[r * QST + c];
            d[0] = qv.x * 0.125f; d[1] = qv.y * 0.125f;
            d[2] = qv.z * 0.125f; d[3] = qv.w * 0.125f;
        }
    }
    __syncthreads();

    // ---- hoist Q fragments: 2 m-tiles x 8 kchunks ----
    uint32_t aq[2][8][4];
#pragma unroll
    for (int mi = 0; mi < 2; mi++) {
        const int base = wr + mi * 16;
#pragma unroll
        for (int kc = 0; kc < 8; kc++) {
            const int kk = kc * 8;
            aq[mi][kc][0] = __float_as_uint(Ps[(base + g) * QST + kk + tg]);
            aq[mi][kc][1] = __float_as_uint(Ps[(base + g + 8) * QST + kk + tg]);
            aq[mi][kc][2] = __float_as_uint(Ps[(base + g) * QST + kk + tg + 4]);
            aq[mi][kc][3] = __float_as_uint(Ps[(base + g + 8) * QST + kk + tg + 4]);
        }
    }
    __syncthreads();   // Ps now free for P

    // ---- K/V staging ----
    const int srow = tid >> 4;
    const int sq   = (tid & 15) * 4;
    auto stage_kv = [&](int kb, int buf) {
        const int kn = kb * 64;
        const uint32_t kBase = sb + (uint32_t)(PS_SZ + buf * KBUF) * 4;
        const uint32_t vBase = sb + (uint32_t)(PS_SZ + 2 * KBUF + buf * VBUF) * 4;
#pragma unroll
        for (int p = 0; p < 8; p++) {
            int r = srow + p * 8;
            cpa16(kBase + (uint32_t)(r * KSTK + sq) * 4, &Kp[(size_t)(kn + r) * ROWK + sq]);
            cpa16(vBase + (uint32_t)(r * KSTV + sq) * 4, &Vp[(size_t)(kn + r) * ROWK + sq]);
        }
    };

    float m_i[2][2] = {{-1e30f, -1e30f}, {-1e30f, -1e30f}};
    float l_i[2][2] = {{0.0f, 0.0f}, {0.0f, 0.0f}};
    float o[2][8][4];
#pragma unroll
    for (int mi = 0; mi < 2; mi++)
#pragma unroll
        for (int nt = 0; nt < 8; nt++)
#pragma unroll
            for (int j = 0; j < 4; j++) o[mi][nt][j] = 0.0f;

    const int kbmax = 2 * qb + 1;
    stage_kv(0, 0);
    cpa_commit();

    for (int kb = 0; kb <= kbmax; kb++) {
        const int kn  = kb * 64;
        const int buf = kb & 1;
        if (kb < kbmax) {
            stage_kv(kb + 1, buf ^ 1);
            cpa_commit();
            cpa_wait<1>();
        } else {
            cpa_wait<0>();
        }
        __syncthreads();

        const uint32_t* Ks = reinterpret_cast<const uint32_t*>(buf ? Kb1 : Kb0);
        const uint32_t* Vs = reinterpret_cast<const uint32_t*>(buf ? Vb1 : Vb0);

        // ---- S = (Q/8) K^T : both m-tiles share each B fragment ----
        float s[2][8][4];
#pragma unroll
        for (int mi = 0; mi < 2; mi++)
#pragma unroll
            for (int nt = 0; nt < 8; nt++)
#pragma unroll
                for (int j = 0; j < 4; j++) s[mi][nt][j] = 0.0f;

#pragma unroll
        for (int kc = 0; kc < 8; kc++) {
            const int kk = kc * 8;
#pragma unroll
            for (int nt = 0; nt < 8; nt++) {
                uint32_t b[2];
                b[0] = Ks[(nt * 8 + g) * KSTK + kk + tg];
                b[1] = Ks[(nt * 8 + g) * KSTK + kk + tg + 4];
                mma_tf32(s[0][nt], aq[0][kc], b);
                mma_tf32(s[1][nt], aq[1][kc], b);
            }
        }

        // ---- online softmax per m-tile ----
        const bool diag = (kn + 63 > q0);
#pragma unroll
        for (int mi = 0; mi < 2; mi++) {
            const int r0 = q0 + wr + mi * 16 + g;
            const int r1 = r0 + 8;
            float mx0 = -1e30f, mx1 = -1e30f;
#pragma unroll
            for (int nt = 0; nt < 8; nt++) {
                int cc = kn + nt * 8 + 2 * tg;
                float v0 = s[mi][nt][0], v1 = s[mi][nt][1];
                float v2 = s[mi][nt][2], v3 = s[mi][nt][3];
                if (diag) {
                    if (cc > r0)     v0 = -1e30f;
                    if (cc + 1 > r0) v1 = -1e30f;
                    if (cc > r1)     v2 = -1e30f;
                    if (cc + 1 > r1) v3 = -1e30f;
                }
                s[mi][nt][0] = v0; s[mi][nt][1] = v1;
                s[mi][nt][2] = v2; s[mi][nt][3] = v3;
                mx0 = fmaxf(mx0, fmaxf(v0, v1));
                mx1 = fmaxf(mx1, fmaxf(v2, v3));
            }
            mx0 = fmaxf(mx0, __shfl_xor_sync(0xffffffffu, mx0, 1));
            mx0 = fmaxf(mx0, __shfl_xor_sync(0xffffffffu, mx0, 2));
            mx1 = fmaxf(mx1, __shfl_xor_sync(0xffffffffu, mx1, 1));
            mx1 = fmaxf(mx1, __shfl_xor_sync(0xffffffffu, mx1, 2));

            float mn0 = fmaxf(m_i[mi][0], mx0), mn1 = fmaxf(m_i[mi][1], mx1);
            float al0 = __expf(m_i[mi][0] - mn0), al1 = __expf(m_i[mi][1] - mn1);
            float ps0 = 0.0f, ps1 = 0.0f;
            const int pr0 = (wr + mi * 16 + g) * QST;
            const int pr1 = pr0 + 8 * QST;
#pragma unroll
            for (int nt = 0; nt < 8; nt++) {
                float p0 = __expf(s[mi][nt][0] - mn0);
                float p1 = __expf(s[mi][nt][1] - mn0);
                float p2 = __expf(s[mi][nt][2] - mn1);
                float p3 = __expf(s[mi][nt][3] - mn1);
                ps0 += p0 + p1; ps1 += p2 + p3;
                int cc = nt * 8 + 2 * tg;
                Ps[pr0 + cc]     = __uint_as_float(f2tf32(p0));
                Ps[pr0 + cc + 1] = __uint_as_float(f2tf32(p1));
                Ps[pr1 + cc]     = __uint_as_float(f2tf32(p2));
                Ps[pr1 + cc + 1] = __uint_as_float(f2tf32(p3));
                o[mi][nt][0] *= al0; o[mi][nt][1] *= al0;
                o[mi][nt][2] *= al1; o[mi][nt][3] *= al1;
            }
            ps0 += __shfl_xor_sync(0xffffffffu, ps0, 1);
            ps0 += __shfl_xor_sync(0xffffffffu, ps0, 2);
            ps1 += __shfl_xor_sync(0xffffffffu, ps1, 1);
            ps1 += __shfl_xor_sync(0xffffffffu, ps1, 2);
            l_i[mi][0] = l_i[mi][0] * al0 + ps0;
            l_i[mi][1] = l_i[mi][1] * al1 + ps1;
            m_i[mi][0] = mn0; m_i[mi][1] = mn1;
        }
        __syncwarp();

        // ---- O += P V : shared B fragments across both m-tiles ----
        const uint32_t* Pu = reinterpret_cast<const uint32_t*>(Ps);
#pragma unroll
        for (int kc = 0; kc < 8; kc++) {
            const int kk = kc * 8;
            uint32_t a[2][4];
#pragma unroll
            for (int mi = 0; mi < 2; mi++) {
                const int base = wr + mi * 16;
                a[mi][0] = Pu[(base + g) * QST + kk + tg];
                a[mi][1] = Pu[(base + g + 8) * QST + kk + tg];
                a[mi][2] = Pu[(base + g) * QST + kk + tg + 4];
                a[mi][3] = Pu[(base + g + 8) * QST + kk + tg + 4];
            }
#pragma unroll
            for (int nt = 0; nt < 8; nt++) {
                uint32_t b[2];
                b[0] = Vs[(kk + tg) * KSTV + nt * 8 + g];
                b[1] = Vs[(kk + tg + 4) * KSTV + nt * 8 + g];
                mma_tf32(o[0][nt], a[0], b);
                mma_tf32(o[1][nt], a[1], b);
            }
        }
        __syncthreads();
    }

    // ---- epilogue ----
#pragma unroll
    for (int mi = 0; mi < 2; mi++) {
        const float inv0 = 1.0f / l_i[mi][0];
        const float inv1 = 1.0f / l_i[mi][1];
        const size_t row0 = (size_t)(q0 + wr + mi * 16 + g) * ROWQ;
        const size_t row1 = row0 + 8 * ROWQ;
#pragma unroll
        for (int nt = 0; nt < 8; nt++) {
            int cc = nt * 8 + 2 * tg;
            *reinterpret_cast<float2*>(&Op[row0 + cc]) =
                make_float2(rtf(o[mi][nt][0] * inv0), rtf(o[mi][nt][1] * inv0));
            *reinterpret_cast<float2*>(&Op[row1 + cc]) =
                make_float2(rtf(o[mi][nt][2] * inv1), rtf(o[mi][nt][3] * inv1));
        }
    }
}

// ================= launch =====================================================
extern "C" void kernel_launch(void* const* d_in, const int* in_sizes, int n_in,
                              void* d_out, int out_size)
{
    const float* x  = (const float*)d_in[0];
    const float* Wq = (const float*)d_in[1];
    const float* Wk = (const float*)d_in[2];
    const float* Wv = (const float*)d_in[3];
    const float* Wo = (const float*)d_in[4];
    float* out = (float*)d_out;

    cudaFuncSetAttribute(flash_mma, cudaFuncAttributeMaxDynamicSharedMemorySize, FA_SMEM);
    cudaFuncSetAttribute(qkv_mma,   cudaFuncAttributeMaxDynamicSharedMemorySize, GEMM_SMEM);
    cudaFuncSetAttribute(oproj_mma, cudaFuncAttributeMaxDynamicSharedMemorySize, GEMM_SMEM);

    round_x<<<MROWS * EMB / (512 * 4), 512>>>(x);
    transpose_all<<<dim3(80, 32), dim3(32, 32)>>>(Wq, Wk, Wv, Wo);

    qkv_mma<<<dim3(12, 32), 128, GEMM_SMEM>>>();
    flash_mma<<<dim3(32, 16), 128, FA_SMEM>>>();
    oproj_mma<<<dim3(8, 32), 128, GEMM_SMEM>>>(out);
}